// round 1
// baseline (speedup 1.0000x reference)
#include <cuda_runtime.h>
#include <cuda_bf16.h>
#include <math_constants.h>

// Problem constants (fixed by the reference)
#define NN 50000
#define EE 1200000
#define DD 128
#define RR 6
#define NEG_SLOPE 0.2f

// ---------------- scratch (no allocations allowed) ----------------
__device__ float g_hx[(size_t)RR * NN * DD];   // 153.6 MB: W_r x_n
__device__ float g_nq[RR * NN];
__device__ float g_nk[RR * NN];
__device__ float g_eval[EE];                   // logits, then exp values (CSR order)
__device__ int   g_csr[EE];                    // edge ids sorted by dst
__device__ int   g_rowstart[NN + 1];
__device__ int   g_cursor[NN];
__device__ int   g_counts[NN];

// ---------------- init: zero the histogram ----------------
__global__ void init_counts_kernel() {
    int i = blockIdx.x * blockDim.x + threadIdx.x;
    if (i < NN) g_counts[i] = 0;
}

// ---------------- histogram of dst ----------------
__global__ void hist_kernel(const int* __restrict__ ei) {
    int e = blockIdx.x * blockDim.x + threadIdx.x;
    if (e < EE) atomicAdd(&g_counts[ei[EE + e]], 1);
}

// ---------------- single-block exclusive scan over N counts ----------------
__global__ void scan_kernel() {
    __shared__ int sums[1024];
    const int t = threadIdx.x;
    const int CH = (NN + 1023) / 1024;
    int base = t * CH;
    int s = 0;
    for (int i = 0; i < CH; i++) {
        int idx = base + i;
        if (idx < NN) s += g_counts[idx];
    }
    sums[t] = s;
    __syncthreads();
    // Hillis-Steele inclusive scan
    for (int off = 1; off < 1024; off <<= 1) {
        int v = (t >= off) ? sums[t - off] : 0;
        __syncthreads();
        sums[t] += v;
        __syncthreads();
    }
    int run = (t == 0) ? 0 : sums[t - 1];
    for (int i = 0; i < CH; i++) {
        int idx = base + i;
        if (idx < NN) {
            g_rowstart[idx] = run;
            g_cursor[idx]   = run;
            run += g_counts[idx];
        }
    }
    if (t == 1023) g_rowstart[NN] = EE;
}

// ---------------- scatter edge ids into CSR order ----------------
__global__ void scatter_kernel(const int* __restrict__ ei) {
    int e = blockIdx.x * blockDim.x + threadIdx.x;
    if (e < EE) {
        int dst = ei[EE + e];
        int pos = atomicAdd(&g_cursor[dst], 1);
        g_csr[pos] = e;
    }
}

// ---------------- GEMM: hx[r] = x @ W[r], fused nq/nk epilogue ----------------
// BM=64, BN=128 (full D), BK=32. 256 threads, each computes 4x8 outputs.
#define BM 64
#define BK 32
__global__ __launch_bounds__(256) void gemm_kernel(
    const float* __restrict__ x, const float* __restrict__ w,
    const float* __restrict__ qv, const float* __restrict__ kv)
{
    __shared__ float Xs[BM][BK];      // 8 KB
    __shared__ float Ws[BK][DD];      // 16 KB
    const int r  = blockIdx.y;
    const int m0 = blockIdx.x * BM;
    const float* W = w + (size_t)r * DD * DD;
    const int t  = threadIdx.x;
    const int tr = t >> 4;            // 0..15 (row group of 4)
    const int tc = t & 15;            // 0..15 (col group of 8)

    float acc[4][8];
#pragma unroll
    for (int i = 0; i < 4; i++)
#pragma unroll
        for (int j = 0; j < 8; j++) acc[i][j] = 0.f;

    for (int k0 = 0; k0 < DD; k0 += BK) {
        // load X tile (64 rows x 32 cols) : 512 float4, 2 per thread
#pragma unroll
        for (int i = t; i < BM * BK / 4; i += 256) {
            int row = i >> 3;
            int c4  = i & 7;
            int gn  = m0 + row;
            float4 v = make_float4(0.f, 0.f, 0.f, 0.f);
            if (gn < NN) v = *(const float4*)&x[(size_t)gn * DD + k0 + c4 * 4];
            *(float4*)&Xs[row][c4 * 4] = v;
        }
        // load W tile (32 rows x 128 cols) : 1024 float4, 4 per thread
#pragma unroll
        for (int i = t; i < BK * DD / 4; i += 256) {
            int row = i >> 5;
            int c4  = i & 31;
            *(float4*)&Ws[row][c4 * 4] = *(const float4*)&W[(size_t)(k0 + row) * DD + c4 * 4];
        }
        __syncthreads();
#pragma unroll
        for (int k = 0; k < BK; ++k) {
            float xv[4], wv[8];
#pragma unroll
            for (int i = 0; i < 4; i++) xv[i] = Xs[tr * 4 + i][k];
#pragma unroll
            for (int j = 0; j < 8; j++) wv[j] = Ws[k][tc * 8 + j];
#pragma unroll
            for (int i = 0; i < 4; i++)
#pragma unroll
                for (int j = 0; j < 8; j++)
                    acc[i][j] = fmaf(xv[i], wv[j], acc[i][j]);
        }
        __syncthreads();
    }

    // epilogue: store hx and fused q/k dot reductions (across the 16 tc lanes)
    float q8[8], k8[8];
#pragma unroll
    for (int j = 0; j < 8; j++) { q8[j] = qv[tc * 8 + j]; k8[j] = kv[tc * 8 + j]; }

#pragma unroll
    for (int i = 0; i < 4; i++) {
        int gn = m0 + tr * 4 + i;
        bool valid = (gn < NN);
        if (valid) {
            float* dst = g_hx + ((size_t)r * NN + gn) * DD + tc * 8;
            *(float4*)(dst)     = make_float4(acc[i][0], acc[i][1], acc[i][2], acc[i][3]);
            *(float4*)(dst + 4) = make_float4(acc[i][4], acc[i][5], acc[i][6], acc[i][7]);
        }
        float pq = 0.f, pk = 0.f;
#pragma unroll
        for (int j = 0; j < 8; j++) {
            pq = fmaf(acc[i][j], q8[j], pq);
            pk = fmaf(acc[i][j], k8[j], pk);
        }
        // reduce across tc (lanes xor <16 stay within same tr group)
#pragma unroll
        for (int o = 8; o > 0; o >>= 1) {
            pq += __shfl_xor_sync(0xffffffffu, pq, o);
            pk += __shfl_xor_sync(0xffffffffu, pk, o);
        }
        if (valid && tc == 0) {
            g_nq[r * NN + gn] = pq;
            g_nk[r * NN + gn] = pk;
        }
    }
}

// ---------------- per-destination-node softmax + aggregation ----------------
// one warp per node; lane-parallel over D (float4/lane covers 128 floats)
__global__ __launch_bounds__(256) void node_kernel(
    const int* __restrict__ ei, const int* __restrict__ etype,
    const float* __restrict__ x, const float* __restrict__ bias,
    float* __restrict__ out, float* __restrict__ alpha_out)
{
    int warp = (blockIdx.x * blockDim.x + threadIdx.x) >> 5;
    int lane = threadIdx.x & 31;
    if (warp >= NN) return;
    const int n = warp;
    const int s = g_rowstart[n];
    const int e = g_rowstart[n + 1];

    // phase 1: logits + max
    float m = -CUDART_INF_F;
    for (int j = s + lane; j < e; j += 32) {
        int eid = g_csr[j];
        int et  = etype[eid];
        int src = ei[eid];
        float lg = g_nq[et * NN + n] + g_nk[et * NN + src];
        lg = (lg > 0.f) ? lg : NEG_SLOPE * lg;
        g_eval[j] = lg;
        m = fmaxf(m, lg);
    }
#pragma unroll
    for (int o = 16; o > 0; o >>= 1) m = fmaxf(m, __shfl_xor_sync(0xffffffffu, m, o));

    // phase 2: exp + denom
    float dsum = 0.f;
    for (int j = s + lane; j < e; j += 32) {
        float ev = __expf(g_eval[j] - m);
        g_eval[j] = ev;
        dsum += ev;
    }
#pragma unroll
    for (int o = 16; o > 0; o >>= 1) dsum += __shfl_xor_sync(0xffffffffu, dsum, o);
    float invden = 1.f / (dsum + 1e-16f);

    // phase 3: weighted accumulation of hx rows + alpha output
    float4 acc = make_float4(0.f, 0.f, 0.f, 0.f);
    for (int j = s; j < e; ++j) {
        int eid = 0, et = 0, src = 0;
        float ev = 0.f;
        if (lane == 0) {
            eid = g_csr[j];
            et  = etype[eid];
            src = ei[eid];
            ev  = g_eval[j];
        }
        eid = __shfl_sync(0xffffffffu, eid, 0);
        et  = __shfl_sync(0xffffffffu, et, 0);
        src = __shfl_sync(0xffffffffu, src, 0);
        ev  = __shfl_sync(0xffffffffu, ev, 0);
        float a = ev * invden;
        if (lane == 0) alpha_out[eid] = a;
        const float4 h = *(const float4*)&g_hx[((size_t)et * NN + src) * DD + lane * 4];
        acc.x = fmaf(a, h.x, acc.x);
        acc.y = fmaf(a, h.y, acc.y);
        acc.z = fmaf(a, h.z, acc.z);
        acc.w = fmaf(a, h.w, acc.w);
    }

    const float4 b  = *(const float4*)&bias[lane * 4];
    const float4 xr = *(const float4*)&x[(size_t)n * DD + lane * 4];
    float4 o;
    o.x = acc.x + b.x + xr.x;
    o.y = acc.y + b.y + xr.y;
    o.z = acc.z + b.z + xr.z;
    o.w = acc.w + b.w + xr.w;
    *(float4*)&out[(size_t)n * DD + lane * 4] = o;
}

// ---------------- launch ----------------
extern "C" void kernel_launch(void* const* d_in, const int* in_sizes, int n_in,
                              void* d_out, int out_size)
{
    const float* x     = (const float*)d_in[0];
    const int*   ei    = (const int*)  d_in[1];   // [2, E]
    const int*   etype = (const int*)  d_in[2];   // [E]
    const float* w     = (const float*)d_in[3];   // [R, D, D]
    const float* qv    = (const float*)d_in[4];   // [D, 1]
    const float* kv    = (const float*)d_in[5];   // [D, 1]
    const float* bias  = (const float*)d_in[6];   // [D]

    float* out       = (float*)d_out;             // [N, D]
    float* alpha_out = out + (size_t)NN * DD;     // [E]

    // CSR build
    init_counts_kernel<<<(NN + 255) / 256, 256>>>();
    hist_kernel<<<(EE + 255) / 256, 256>>>(ei);
    scan_kernel<<<1, 1024>>>();
    scatter_kernel<<<(EE + 255) / 256, 256>>>(ei);

    // hx = x @ W_r  (+ fused nq/nk)
    dim3 ggrid((NN + BM - 1) / BM, RR);
    gemm_kernel<<<ggrid, 256>>>(x, w, qv, kv);

    // softmax + aggregation, one warp per destination node
    node_kernel<<<(NN * 32 + 255) / 256, 256>>>(ei, etype, x, bias, out, alpha_out);
}

// round 3
// speedup vs baseline: 1.8554x; 1.8554x over previous
#include <cuda_runtime.h>
#include <math_constants.h>
#include <cstdint>

#define NN 50000
#define EE 1200000
#define DD 128
#define RR 6
#define NEG_SLOPE 0.2f

// ---------------- scratch ----------------
__device__ float g_T[(size_t)NN * RR * DD];   // [n][r][d] weighted-x aggregation
__device__ float g_logit[EE];                 // logits in CSR order
__device__ int   g_csr[EE];                   // original edge id, CSR order
__device__ int   g_se[EE];                    // packed src | (et<<20), CSR order
__device__ float g_nqk[NN * 12];              // [n][r*2]=nq, [n][r*2+1]=nk
__device__ float g_cq[RR * DD];               // W_r @ q
__device__ float g_ck[RR * DD];               // W_r @ k
__device__ int   g_rowstart[NN + 1];
__device__ int   g_cursor[NN];
__device__ int   g_counts[NN];

// ---------------- CSR build ----------------
__global__ void init_counts_kernel() {
    int i = blockIdx.x * blockDim.x + threadIdx.x;
    if (i < NN) g_counts[i] = 0;
}

__global__ void hist_kernel(const int* __restrict__ ei) {
    int e = blockIdx.x * blockDim.x + threadIdx.x;
    if (e < EE) atomicAdd(&g_counts[ei[EE + e]], 1);
}

__global__ void scan_kernel() {
    __shared__ int sums[1024];
    const int t = threadIdx.x;
    const int CH = (NN + 1023) / 1024;
    int base = t * CH;
    int s = 0;
    for (int i = 0; i < CH; i++) {
        int idx = base + i;
        if (idx < NN) s += g_counts[idx];
    }
    sums[t] = s;
    __syncthreads();
    for (int off = 1; off < 1024; off <<= 1) {
        int v = (t >= off) ? sums[t - off] : 0;
        __syncthreads();
        sums[t] += v;
        __syncthreads();
    }
    int run = (t == 0) ? 0 : sums[t - 1];
    for (int i = 0; i < CH; i++) {
        int idx = base + i;
        if (idx < NN) {
            g_rowstart[idx] = run;
            g_cursor[idx]   = run;
            run += g_counts[idx];
        }
    }
    if (t == 1023) g_rowstart[NN] = EE;
}

__global__ void scatter_kernel(const int* __restrict__ ei, const int* __restrict__ etype) {
    int e = blockIdx.x * blockDim.x + threadIdx.x;
    if (e < EE) {
        int dst = ei[EE + e];
        int pos = atomicAdd(&g_cursor[dst], 1);
        g_csr[pos] = e;
        g_se[pos]  = ei[e] | (etype[e] << 20);
    }
}

// ---------------- cq/ck: one warp per (r,d) row of W ----------------
__global__ __launch_bounds__(256) void cqck_kernel(
    const float* __restrict__ w, const float* __restrict__ q, const float* __restrict__ k)
{
    int warp = (blockIdx.x * blockDim.x + threadIdx.x) >> 5;
    int lane = threadIdx.x & 31;
    if (warp >= RR * DD) return;
    const float* row = w + (size_t)warp * DD;
    float sq = 0.f, sk = 0.f;
#pragma unroll
    for (int o = lane; o < DD; o += 32) {
        float v = row[o];
        sq = fmaf(v, q[o], sq);
        sk = fmaf(v, k[o], sk);
    }
#pragma unroll
    for (int off = 16; off > 0; off >>= 1) {
        sq += __shfl_xor_sync(0xffffffffu, sq, off);
        sk += __shfl_xor_sync(0xffffffffu, sk, off);
    }
    if (lane == 0) { g_cq[warp] = sq; g_ck[warp] = sk; }
}

// ---------------- nq/nk per node: one warp per node ----------------
__global__ __launch_bounds__(256) void nqnk_kernel(const float* __restrict__ x)
{
    int warp = (blockIdx.x * blockDim.x + threadIdx.x) >> 5;
    int lane = threadIdx.x & 31;
    if (warp >= NN) return;
    const int n = warp;
    const float4 xv = *(const float4*)&x[(size_t)n * DD + lane * 4];
#pragma unroll
    for (int r = 0; r < RR; r++) {
        const float4 cq = *(const float4*)&g_cq[r * DD + lane * 4];
        const float4 ck = *(const float4*)&g_ck[r * DD + lane * 4];
        float sq = xv.x * cq.x + xv.y * cq.y + xv.z * cq.z + xv.w * cq.w;
        float sk = xv.x * ck.x + xv.y * ck.y + xv.z * ck.z + xv.w * ck.w;
#pragma unroll
        for (int off = 16; off > 0; off >>= 1) {
            sq += __shfl_xor_sync(0xffffffffu, sq, off);
            sk += __shfl_xor_sync(0xffffffffu, sk, off);
        }
        if (lane == 0) {
            g_nqk[n * 12 + r * 2]     = sq;
            g_nqk[n * 12 + r * 2 + 1] = sk;
        }
    }
}

// ---------------- per-destination softmax + weighted-x aggregation ----------------
__device__ __forceinline__ float sel6(int et, float v0, float v1, float v2,
                                      float v3, float v4, float v5) {
    float v = v0;
    v = (et == 1) ? v1 : v;
    v = (et == 2) ? v2 : v;
    v = (et == 3) ? v3 : v;
    v = (et == 4) ? v4 : v;
    v = (et == 5) ? v5 : v;
    return v;
}

__device__ __forceinline__ void accum6(float4 (&acc)[RR], int et, float a, float4 v) {
    switch (et) {
        case 0: acc[0].x = fmaf(a, v.x, acc[0].x); acc[0].y = fmaf(a, v.y, acc[0].y);
                acc[0].z = fmaf(a, v.z, acc[0].z); acc[0].w = fmaf(a, v.w, acc[0].w); break;
        case 1: acc[1].x = fmaf(a, v.x, acc[1].x); acc[1].y = fmaf(a, v.y, acc[1].y);
                acc[1].z = fmaf(a, v.z, acc[1].z); acc[1].w = fmaf(a, v.w, acc[1].w); break;
        case 2: acc[2].x = fmaf(a, v.x, acc[2].x); acc[2].y = fmaf(a, v.y, acc[2].y);
                acc[2].z = fmaf(a, v.z, acc[2].z); acc[2].w = fmaf(a, v.w, acc[2].w); break;
        case 3: acc[3].x = fmaf(a, v.x, acc[3].x); acc[3].y = fmaf(a, v.y, acc[3].y);
                acc[3].z = fmaf(a, v.z, acc[3].z); acc[3].w = fmaf(a, v.w, acc[3].w); break;
        case 4: acc[4].x = fmaf(a, v.x, acc[4].x); acc[4].y = fmaf(a, v.y, acc[4].y);
                acc[4].z = fmaf(a, v.z, acc[4].z); acc[4].w = fmaf(a, v.w, acc[4].w); break;
        default: acc[5].x = fmaf(a, v.x, acc[5].x); acc[5].y = fmaf(a, v.y, acc[5].y);
                acc[5].z = fmaf(a, v.z, acc[5].z); acc[5].w = fmaf(a, v.w, acc[5].w); break;
    }
}

__global__ __launch_bounds__(256) void node_kernel(
    const float* __restrict__ x, float* __restrict__ alpha_out)
{
    int warp = (blockIdx.x * blockDim.x + threadIdx.x) >> 5;
    int lane = threadIdx.x & 31;
    if (warp >= NN) return;        // uniform per warp
    const int n = warp;
    const int s = g_rowstart[n];
    const int e = g_rowstart[n + 1];

    // per-node nq values: broadcast loads (same address across warp)
    const float nq0 = g_nqk[n * 12 + 0];
    const float nq1 = g_nqk[n * 12 + 2];
    const float nq2 = g_nqk[n * 12 + 4];
    const float nq3 = g_nqk[n * 12 + 6];
    const float nq4 = g_nqk[n * 12 + 8];
    const float nq5 = g_nqk[n * 12 + 10];

    // pass A: logits + lane-local online softmax (uniform trip count)
    float lm = -CUDART_INF_F;   // lane-local max
    float ls = 0.f;             // lane-local sum of exp(lg - lm)
    for (int j0 = s; j0 < e; j0 += 32) {
        int j = j0 + lane;
        bool valid = (j < e);
        if (valid) {
            int se  = g_se[j];
            int src = se & 0xFFFFF;
            int et  = se >> 20;
            float nk = __ldg(&g_nqk[src * 12 + et * 2 + 1]);
            float nq = sel6(et, nq0, nq1, nq2, nq3, nq4, nq5);
            float lg = nq + nk;
            lg = (lg > 0.f) ? lg : NEG_SLOPE * lg;
            g_logit[j] = lg;
            float nlm = fmaxf(lm, lg);
            ls = ls * __expf(lm - nlm) + __expf(lg - nlm);
            lm = nlm;
        }
    }
    // combine lanes: m = max(lm); dsum = sum ls * exp(lm - m)
    float m = lm;
#pragma unroll
    for (int o = 16; o > 0; o >>= 1) m = fmaxf(m, __shfl_xor_sync(0xffffffffu, m, o));
    float contrib = (ls > 0.f) ? ls * __expf(lm - m) : 0.f;
    float dsum = contrib;
#pragma unroll
    for (int o = 16; o > 0; o >>= 1) dsum += __shfl_xor_sync(0xffffffffu, dsum, o);
    const float invden = 1.f / (dsum + 1e-16f);

    // pass B: alpha out + weighted aggregation of raw x rows (uniform loop)
    float4 acc[RR];
#pragma unroll
    for (int r = 0; r < RR; r++) acc[r] = make_float4(0.f, 0.f, 0.f, 0.f);

    for (int base = s; base < e; base += 32) {
        int j = base + lane;
        bool valid = (j < e);
        int se = 0;
        float a = 0.f;
        if (valid) {
            se = g_se[j];
            a  = __expf(g_logit[j] - m) * invden;
            alpha_out[g_csr[j]] = a;
        }
        int cnt = e - base; if (cnt > 32) cnt = 32;
        int rounds = (cnt + 3) & ~3;
        for (int t = 0; t < rounds; t += 4) {
            int   se0 = __shfl_sync(0xffffffffu, se, t);
            int   se1 = __shfl_sync(0xffffffffu, se, t + 1);
            int   se2 = __shfl_sync(0xffffffffu, se, t + 2);
            int   se3 = __shfl_sync(0xffffffffu, se, t + 3);
            float a0  = __shfl_sync(0xffffffffu, a,  t);
            float a1  = __shfl_sync(0xffffffffu, a,  t + 1);
            float a2  = __shfl_sync(0xffffffffu, a,  t + 2);
            float a3  = __shfl_sync(0xffffffffu, a,  t + 3);
            // tail lanes carry a==0, se==0 -> harmless x[0] load contributing 0
            const float4 x0 = __ldg((const float4*)&x[(size_t)(se0 & 0xFFFFF) * DD + lane * 4]);
            const float4 x1 = __ldg((const float4*)&x[(size_t)(se1 & 0xFFFFF) * DD + lane * 4]);
            const float4 x2 = __ldg((const float4*)&x[(size_t)(se2 & 0xFFFFF) * DD + lane * 4]);
            const float4 x3 = __ldg((const float4*)&x[(size_t)(se3 & 0xFFFFF) * DD + lane * 4]);
            accum6(acc, se0 >> 20, a0, x0);
            accum6(acc, se1 >> 20, a1, x1);
            accum6(acc, se2 >> 20, a2, x2);
            accum6(acc, se3 >> 20, a3, x3);
        }
    }

#pragma unroll
    for (int r = 0; r < RR; r++)
        *(float4*)&g_T[((size_t)n * RR + r) * DD + lane * 4] = acc[r];
}

// ---------------- TF32 tensor-core GEMM: out = T[N,768] @ w[768,128] + bias + x ----------------
__device__ __forceinline__ float tf32r(float v) {
    uint32_t o;
    asm("cvt.rna.tf32.f32 %0, %1;" : "=r"(o) : "f"(v));
    return __uint_as_float(o);
}
__device__ __forceinline__ float4 tf32r4(float4 v) {
    return make_float4(tf32r(v.x), tf32r(v.y), tf32r(v.z), tf32r(v.w));
}

#define GBM 128
#define GBK 32
#define APAD 4   // A row stride 36 floats
#define BPAD 8   // B row stride 136 floats

__global__ __launch_bounds__(256) void gemm_tc_kernel(
    const float* __restrict__ w, const float* __restrict__ x,
    const float* __restrict__ bias, float* __restrict__ out)
{
    __shared__ float As[GBM][GBK + APAD];
    __shared__ float Bs[GBK][DD + BPAD];

    const int m0   = blockIdx.x * GBM;
    const int t    = threadIdx.x;
    const int warp = t >> 5;
    const int lane = t & 31;
    const int g    = lane >> 2;   // 0..7
    const int tig  = lane & 3;    // 0..3
    const int R0   = (warp & 3) * 32;   // warp row base in tile
    const int C0   = (warp >> 2) * 64;  // warp col base in tile

    float acc[2][8][4];
#pragma unroll
    for (int mt = 0; mt < 2; mt++)
#pragma unroll
        for (int nt = 0; nt < 8; nt++)
#pragma unroll
            for (int i = 0; i < 4; i++) acc[mt][nt][i] = 0.f;

    for (int k0 = 0; k0 < RR * DD; k0 += GBK) {
        // A tile: 128 x 32 from g_T
#pragma unroll
        for (int i = t; i < GBM * GBK / 4; i += 256) {
            int row = i >> 3, c4 = i & 7;
            int gr = m0 + row;
            float4 v = make_float4(0.f, 0.f, 0.f, 0.f);
            if (gr < NN) v = *(const float4*)&g_T[(size_t)gr * (RR * DD) + k0 + c4 * 4];
            *(float4*)&As[row][c4 * 4] = tf32r4(v);
        }
        // B tile: 32 x 128 from w ([768,128] row-major)
#pragma unroll
        for (int i = t; i < GBK * DD / 4; i += 256) {
            int kk = i >> 5, c4 = i & 31;
            float4 v = *(const float4*)&w[(size_t)(k0 + kk) * DD + c4 * 4];
            *(float4*)&Bs[kk][c4 * 4] = tf32r4(v);
        }
        __syncthreads();

#pragma unroll
        for (int ks = 0; ks < GBK; ks += 8) {
            uint32_t af[2][4];
#pragma unroll
            for (int mt = 0; mt < 2; mt++) {
                int rb = R0 + mt * 16;
                af[mt][0] = __float_as_uint(As[rb + g][ks + tig]);
                af[mt][1] = __float_as_uint(As[rb + g + 8][ks + tig]);
                af[mt][2] = __float_as_uint(As[rb + g][ks + tig + 4]);
                af[mt][3] = __float_as_uint(As[rb + g + 8][ks + tig + 4]);
            }
            uint32_t bf[8][2];
#pragma unroll
            for (int nt = 0; nt < 8; nt++) {
                int cb = C0 + nt * 8 + g;
                bf[nt][0] = __float_as_uint(Bs[ks + tig][cb]);
                bf[nt][1] = __float_as_uint(Bs[ks + tig + 4][cb]);
            }
#pragma unroll
            for (int mt = 0; mt < 2; mt++)
#pragma unroll
                for (int nt = 0; nt < 8; nt++) {
                    asm volatile(
                        "mma.sync.aligned.m16n8k8.row.col.f32.tf32.tf32.f32 "
                        "{%0,%1,%2,%3}, {%4,%5,%6,%7}, {%8,%9}, {%0,%1,%2,%3};"
                        : "+f"(acc[mt][nt][0]), "+f"(acc[mt][nt][1]),
                          "+f"(acc[mt][nt][2]), "+f"(acc[mt][nt][3])
                        : "r"(af[mt][0]), "r"(af[mt][1]), "r"(af[mt][2]), "r"(af[mt][3]),
                          "r"(bf[nt][0]), "r"(bf[nt][1]));
                }
        }
        __syncthreads();
    }

    // epilogue: + bias + x residual
#pragma unroll
    for (int mt = 0; mt < 2; mt++) {
        int row0 = m0 + R0 + mt * 16 + g;
        int row1 = row0 + 8;
#pragma unroll
        for (int nt = 0; nt < 8; nt++) {
            int col = C0 + nt * 8 + 2 * tig;
            float2 b = *(const float2*)&bias[col];
            if (row0 < NN) {
                const float2 xr = *(const float2*)&x[(size_t)row0 * DD + col];
                float2 o;
                o.x = acc[mt][nt][0] + b.x + xr.x;
                o.y = acc[mt][nt][1] + b.y + xr.y;
                *(float2*)&out[(size_t)row0 * DD + col] = o;
            }
            if (row1 < NN) {
                const float2 xr = *(const float2*)&x[(size_t)row1 * DD + col];
                float2 o;
                o.x = acc[mt][nt][2] + b.x + xr.x;
                o.y = acc[mt][nt][3] + b.y + xr.y;
                *(float2*)&out[(size_t)row1 * DD + col] = o;
            }
        }
    }
}

// ---------------- launch ----------------
extern "C" void kernel_launch(void* const* d_in, const int* in_sizes, int n_in,
                              void* d_out, int out_size)
{
    const float* x     = (const float*)d_in[0];
    const int*   ei    = (const int*)  d_in[1];   // [2, E]
    const int*   etype = (const int*)  d_in[2];   // [E]
    const float* w     = (const float*)d_in[3];   // [R, D, D] == [768,128]
    const float* qv    = (const float*)d_in[4];   // [D, 1]
    const float* kv    = (const float*)d_in[5];   // [D, 1]
    const float* bias  = (const float*)d_in[6];   // [D]

    float* out       = (float*)d_out;             // [N, D]
    float* alpha_out = out + (size_t)NN * DD;     // [E]

    // CSR build
    init_counts_kernel<<<(NN + 255) / 256, 256>>>();
    hist_kernel<<<(EE + 255) / 256, 256>>>(ei);
    scan_kernel<<<1, 1024>>>();
    scatter_kernel<<<(EE + 255) / 256, 256>>>(ei, etype);

    // attention projection tables
    cqck_kernel<<<(RR * DD * 32 + 255) / 256, 256>>>(w, qv, kv);
    nqnk_kernel<<<(NN * 32 + 255) / 256, 256>>>(x);

    // softmax + weighted-x aggregation into T
    node_kernel<<<(NN * 32 + 255) / 256, 256>>>(x, alpha_out);

    // out = T @ Wcat + bias + x  (tf32 tensor cores)
    gemm_tc_kernel<<<(NN + GBM - 1) / GBM, 256>>>(w, x, bias, out);
}

// round 4
// speedup vs baseline: 2.1418x; 1.1544x over previous
#include <cuda_runtime.h>
#include <cuda_bf16.h>
#include <math_constants.h>
#include <cstdint>

#define NN 50000
#define EE 1200000
#define DD 128
#define RR 6
#define KK (RR * DD)   // 768
#define NEG_SLOPE 0.2f

// ---------------- scratch ----------------
__device__ __nv_bfloat16 g_Tb[(size_t)NN * KK];  // [n][r*128+d] bf16 (76.8 MB)
__device__ __nv_bfloat16 g_wt[(size_t)DD * KK];  // W^T as [n_out=128][k=768] bf16
__device__ float g_logit[EE];
__device__ int   g_csr[EE];
__device__ int   g_se[EE];
__device__ float g_nqk[NN * 12];
__device__ float g_cq[KK];
__device__ float g_ck[KK];
__device__ int   g_rowstart[NN + 1];
__device__ int   g_cursor[NN];
__device__ int   g_counts[NN];

// ---------------- CSR build ----------------
__global__ void init_counts_kernel() {
    int i = blockIdx.x * blockDim.x + threadIdx.x;
    if (i < NN) g_counts[i] = 0;
}

__global__ void hist_kernel(const int* __restrict__ ei) {
    int e = blockIdx.x * blockDim.x + threadIdx.x;
    if (e < EE) atomicAdd(&g_counts[ei[EE + e]], 1);
}

__global__ void scan_kernel() {
    __shared__ int sums[1024];
    const int t = threadIdx.x;
    const int CH = (NN + 1023) / 1024;
    int base = t * CH;
    int s = 0;
    for (int i = 0; i < CH; i++) {
        int idx = base + i;
        if (idx < NN) s += g_counts[idx];
    }
    sums[t] = s;
    __syncthreads();
    for (int off = 1; off < 1024; off <<= 1) {
        int v = (t >= off) ? sums[t - off] : 0;
        __syncthreads();
        sums[t] += v;
        __syncthreads();
    }
    int run = (t == 0) ? 0 : sums[t - 1];
    for (int i = 0; i < CH; i++) {
        int idx = base + i;
        if (idx < NN) {
            g_rowstart[idx] = run;
            g_cursor[idx]   = run;
            run += g_counts[idx];
        }
    }
    if (t == 1023) g_rowstart[NN] = EE;
}

__global__ void scatter_kernel(const int* __restrict__ ei, const int* __restrict__ etype) {
    int e = blockIdx.x * blockDim.x + threadIdx.x;
    if (e < EE) {
        int dst = ei[EE + e];
        int pos = atomicAdd(&g_cursor[dst], 1);
        g_csr[pos] = e;
        g_se[pos]  = ei[e] | (etype[e] << 20);
    }
}

// ---------------- W transpose to bf16: g_wt[n][k] = w[k][n] ----------------
__global__ void wt_kernel(const float* __restrict__ w) {
    __shared__ float tile[32][33];
    int k0 = blockIdx.y * 32;   // 24 blocks
    int n0 = blockIdx.x * 32;   // 4 blocks
    int tx = threadIdx.x, ty = threadIdx.y;  // 32 x 8
#pragma unroll
    for (int i = 0; i < 4; i++)
        tile[ty + i * 8][tx] = w[(size_t)(k0 + ty + i * 8) * DD + n0 + tx];
    __syncthreads();
#pragma unroll
    for (int i = 0; i < 4; i++)
        g_wt[(size_t)(n0 + ty + i * 8) * KK + k0 + tx] =
            __float2bfloat16_rn(tile[tx][ty + i * 8]);
}

// ---------------- cq/ck ----------------
__global__ __launch_bounds__(256) void cqck_kernel(
    const float* __restrict__ w, const float* __restrict__ q, const float* __restrict__ k)
{
    int warp = (blockIdx.x * blockDim.x + threadIdx.x) >> 5;
    int lane = threadIdx.x & 31;
    if (warp >= KK) return;
    const float* row = w + (size_t)warp * DD;
    float sq = 0.f, sk = 0.f;
#pragma unroll
    for (int o = lane; o < DD; o += 32) {
        float v = row[o];
        sq = fmaf(v, q[o], sq);
        sk = fmaf(v, k[o], sk);
    }
#pragma unroll
    for (int off = 16; off > 0; off >>= 1) {
        sq += __shfl_xor_sync(0xffffffffu, sq, off);
        sk += __shfl_xor_sync(0xffffffffu, sk, off);
    }
    if (lane == 0) { g_cq[warp] = sq; g_ck[warp] = sk; }
}

// ---------------- nq/nk ----------------
__global__ __launch_bounds__(256) void nqnk_kernel(const float* __restrict__ x)
{
    int warp = (blockIdx.x * blockDim.x + threadIdx.x) >> 5;
    int lane = threadIdx.x & 31;
    if (warp >= NN) return;
    const int n = warp;
    const float4 xv = *(const float4*)&x[(size_t)n * DD + lane * 4];
#pragma unroll
    for (int r = 0; r < RR; r++) {
        const float4 cq = *(const float4*)&g_cq[r * DD + lane * 4];
        const float4 ck = *(const float4*)&g_ck[r * DD + lane * 4];
        float sq = xv.x * cq.x + xv.y * cq.y + xv.z * cq.z + xv.w * cq.w;
        float sk = xv.x * ck.x + xv.y * ck.y + xv.z * ck.z + xv.w * ck.w;
#pragma unroll
        for (int off = 16; off > 0; off >>= 1) {
            sq += __shfl_xor_sync(0xffffffffu, sq, off);
            sk += __shfl_xor_sync(0xffffffffu, sk, off);
        }
        if (lane == 0) {
            g_nqk[n * 12 + r * 2]     = sq;
            g_nqk[n * 12 + r * 2 + 1] = sk;
        }
    }
}

// ---------------- node softmax + weighted-x aggregation -> bf16 T ----------------
__device__ __forceinline__ float sel6(int et, float v0, float v1, float v2,
                                      float v3, float v4, float v5) {
    float v = v0;
    v = (et == 1) ? v1 : v;
    v = (et == 2) ? v2 : v;
    v = (et == 3) ? v3 : v;
    v = (et == 4) ? v4 : v;
    v = (et == 5) ? v5 : v;
    return v;
}

__device__ __forceinline__ void accum6(float4 (&acc)[RR], int et, float a, float4 v) {
    switch (et) {
        case 0: acc[0].x = fmaf(a, v.x, acc[0].x); acc[0].y = fmaf(a, v.y, acc[0].y);
                acc[0].z = fmaf(a, v.z, acc[0].z); acc[0].w = fmaf(a, v.w, acc[0].w); break;
        case 1: acc[1].x = fmaf(a, v.x, acc[1].x); acc[1].y = fmaf(a, v.y, acc[1].y);
                acc[1].z = fmaf(a, v.z, acc[1].z); acc[1].w = fmaf(a, v.w, acc[1].w); break;
        case 2: acc[2].x = fmaf(a, v.x, acc[2].x); acc[2].y = fmaf(a, v.y, acc[2].y);
                acc[2].z = fmaf(a, v.z, acc[2].z); acc[2].w = fmaf(a, v.w, acc[2].w); break;
        case 3: acc[3].x = fmaf(a, v.x, acc[3].x); acc[3].y = fmaf(a, v.y, acc[3].y);
                acc[3].z = fmaf(a, v.z, acc[3].z); acc[3].w = fmaf(a, v.w, acc[3].w); break;
        case 4: acc[4].x = fmaf(a, v.x, acc[4].x); acc[4].y = fmaf(a, v.y, acc[4].y);
                acc[4].z = fmaf(a, v.z, acc[4].z); acc[4].w = fmaf(a, v.w, acc[4].w); break;
        default: acc[5].x = fmaf(a, v.x, acc[5].x); acc[5].y = fmaf(a, v.y, acc[5].y);
                acc[5].z = fmaf(a, v.z, acc[5].z); acc[5].w = fmaf(a, v.w, acc[5].w); break;
    }
}

__global__ __launch_bounds__(256) void node_kernel(
    const float* __restrict__ x, float* __restrict__ alpha_out)
{
    int warp = (blockIdx.x * blockDim.x + threadIdx.x) >> 5;
    int lane = threadIdx.x & 31;
    if (warp >= NN) return;
    const int n = warp;
    const int s = g_rowstart[n];
    const int e = g_rowstart[n + 1];

    const float nq0 = g_nqk[n * 12 + 0];
    const float nq1 = g_nqk[n * 12 + 2];
    const float nq2 = g_nqk[n * 12 + 4];
    const float nq3 = g_nqk[n * 12 + 6];
    const float nq4 = g_nqk[n * 12 + 8];
    const float nq5 = g_nqk[n * 12 + 10];

    // pass A: logits + lane-local online softmax
    float lm = -CUDART_INF_F;
    float ls = 0.f;
    for (int j0 = s; j0 < e; j0 += 32) {
        int j = j0 + lane;
        if (j < e) {
            int se  = g_se[j];
            int src = se & 0xFFFFF;
            int et  = se >> 20;
            float nk = __ldg(&g_nqk[src * 12 + et * 2 + 1]);
            float nq = sel6(et, nq0, nq1, nq2, nq3, nq4, nq5);
            float lg = nq + nk;
            lg = (lg > 0.f) ? lg : NEG_SLOPE * lg;
            g_logit[j] = lg;
            float nlm = fmaxf(lm, lg);
            ls = ls * __expf(lm - nlm) + __expf(lg - nlm);
            lm = nlm;
        }
    }
    float m = lm;
#pragma unroll
    for (int o = 16; o > 0; o >>= 1) m = fmaxf(m, __shfl_xor_sync(0xffffffffu, m, o));
    float contrib = (ls > 0.f) ? ls * __expf(lm - m) : 0.f;
    float dsum = contrib;
#pragma unroll
    for (int o = 16; o > 0; o >>= 1) dsum += __shfl_xor_sync(0xffffffffu, dsum, o);
    const float invden = 1.f / (dsum + 1e-16f);

    // pass B: alpha + weighted x aggregation
    float4 acc[RR];
#pragma unroll
    for (int r = 0; r < RR; r++) acc[r] = make_float4(0.f, 0.f, 0.f, 0.f);

    for (int base = s; base < e; base += 32) {
        int j = base + lane;
        int se = 0;
        float a = 0.f;
        if (j < e) {
            se = g_se[j];
            a  = __expf(g_logit[j] - m) * invden;
            alpha_out[g_csr[j]] = a;
        }
        int cnt = e - base; if (cnt > 32) cnt = 32;
        int rounds = (cnt + 3) & ~3;
        for (int t = 0; t < rounds; t += 4) {
            int   se0 = __shfl_sync(0xffffffffu, se, t);
            int   se1 = __shfl_sync(0xffffffffu, se, t + 1);
            int   se2 = __shfl_sync(0xffffffffu, se, t + 2);
            int   se3 = __shfl_sync(0xffffffffu, se, t + 3);
            float a0  = __shfl_sync(0xffffffffu, a,  t);
            float a1  = __shfl_sync(0xffffffffu, a,  t + 1);
            float a2  = __shfl_sync(0xffffffffu, a,  t + 2);
            float a3  = __shfl_sync(0xffffffffu, a,  t + 3);
            const float4 x0 = __ldg((const float4*)&x[(size_t)(se0 & 0xFFFFF) * DD + lane * 4]);
            const float4 x1 = __ldg((const float4*)&x[(size_t)(se1 & 0xFFFFF) * DD + lane * 4]);
            const float4 x2 = __ldg((const float4*)&x[(size_t)(se2 & 0xFFFFF) * DD + lane * 4]);
            const float4 x3 = __ldg((const float4*)&x[(size_t)(se3 & 0xFFFFF) * DD + lane * 4]);
            accum6(acc, se0 >> 20, a0, x0);
            accum6(acc, se1 >> 20, a1, x1);
            accum6(acc, se2 >> 20, a2, x2);
            accum6(acc, se3 >> 20, a3, x3);
        }
    }

    // store T row in bf16
#pragma unroll
    for (int r = 0; r < RR; r++) {
        __nv_bfloat162 lo = __floats2bfloat162_rn(acc[r].x, acc[r].y);
        __nv_bfloat162 hi = __floats2bfloat162_rn(acc[r].z, acc[r].w);
        uint2 pk = make_uint2(*(uint32_t*)&lo, *(uint32_t*)&hi);
        *(uint2*)&g_Tb[(size_t)n * KK + r * DD + lane * 4] = pk;
    }
}

// ---------------- bf16 tensor-core GEMM: out = T @ W + bias + x ----------------
// BM=128, BK=64, N=128; smem [m][72] / [n][72] bf16 (stride 36 words, conflict-free)
#define GBM 128
#define GBK 64
#define SSTR 72

__global__ __launch_bounds__(256) void gemm_tc_kernel(
    const float* __restrict__ x, const float* __restrict__ bias, float* __restrict__ out)
{
    __shared__ __nv_bfloat16 As[GBM][SSTR];
    __shared__ __nv_bfloat16 Bs[DD][SSTR];   // Bs[n][k] (from g_wt)

    const int m0   = blockIdx.x * GBM;
    const int t    = threadIdx.x;
    const int warp = t >> 5;
    const int lane = t & 31;
    const int g    = lane >> 2;
    const int tig  = lane & 3;
    const int R0   = (warp & 3) * 32;
    const int C0   = (warp >> 2) * 64;

    float acc[2][8][4];
#pragma unroll
    for (int mt = 0; mt < 2; mt++)
#pragma unroll
        for (int nt = 0; nt < 8; nt++)
#pragma unroll
            for (int i = 0; i < 4; i++) acc[mt][nt][i] = 0.f;

    for (int k0 = 0; k0 < KK; k0 += GBK) {
        // A tile: 128 rows x 64 bf16 (128 B/row) from g_Tb
#pragma unroll
        for (int i = t; i < GBM * GBK / 8; i += 256) {
            int row = i >> 3, c8 = i & 7;
            int gr = m0 + row;
            uint4 v = make_uint4(0, 0, 0, 0);
            if (gr < NN) v = *(const uint4*)&g_Tb[(size_t)gr * KK + k0 + c8 * 8];
            *(uint4*)&As[row][c8 * 8] = v;
        }
        // B tile: 128 rows x 64 bf16 from g_wt
#pragma unroll
        for (int i = t; i < DD * GBK / 8; i += 256) {
            int row = i >> 3, c8 = i & 7;
            *(uint4*)&Bs[row][c8 * 8] = *(const uint4*)&g_wt[(size_t)row * KK + k0 + c8 * 8];
        }
        __syncthreads();

#pragma unroll
        for (int ks = 0; ks < GBK; ks += 16) {
            uint32_t af[2][4];
#pragma unroll
            for (int mt = 0; mt < 2; mt++) {
                int rb = R0 + mt * 16;
                af[mt][0] = *(const uint32_t*)&As[rb + g][ks + 2 * tig];
                af[mt][1] = *(const uint32_t*)&As[rb + g + 8][ks + 2 * tig];
                af[mt][2] = *(const uint32_t*)&As[rb + g][ks + 8 + 2 * tig];
                af[mt][3] = *(const uint32_t*)&As[rb + g + 8][ks + 8 + 2 * tig];
            }
#pragma unroll
            for (int nt = 0; nt < 8; nt++) {
                int cb = C0 + nt * 8 + g;
                uint32_t b0 = *(const uint32_t*)&Bs[cb][ks + 2 * tig];
                uint32_t b1 = *(const uint32_t*)&Bs[cb][ks + 8 + 2 * tig];
#pragma unroll
                for (int mt = 0; mt < 2; mt++) {
                    asm volatile(
                        "mma.sync.aligned.m16n8k16.row.col.f32.bf16.bf16.f32 "
                        "{%0,%1,%2,%3}, {%4,%5,%6,%7}, {%8,%9}, {%0,%1,%2,%3};"
                        : "+f"(acc[mt][nt][0]), "+f"(acc[mt][nt][1]),
                          "+f"(acc[mt][nt][2]), "+f"(acc[mt][nt][3])
                        : "r"(af[mt][0]), "r"(af[mt][1]), "r"(af[mt][2]), "r"(af[mt][3]),
                          "r"(b0), "r"(b1));
                }
            }
        }
        __syncthreads();
    }

    // epilogue: + bias + x residual
#pragma unroll
    for (int mt = 0; mt < 2; mt++) {
        int row0 = m0 + R0 + mt * 16 + g;
        int row1 = row0 + 8;
#pragma unroll
        for (int nt = 0; nt < 8; nt++) {
            int col = C0 + nt * 8 + 2 * tig;
            float2 b = *(const float2*)&bias[col];
            if (row0 < NN) {
                const float2 xr = *(const float2*)&x[(size_t)row0 * DD + col];
                float2 o;
                o.x = acc[mt][nt][0] + b.x + xr.x;
                o.y = acc[mt][nt][1] + b.y + xr.y;
                *(float2*)&out[(size_t)row0 * DD + col] = o;
            }
            if (row1 < NN) {
                const float2 xr = *(const float2*)&x[(size_t)row1 * DD + col];
                float2 o;
                o.x = acc[mt][nt][2] + b.x + xr.x;
                o.y = acc[mt][nt][3] + b.y + xr.y;
                *(float2*)&out[(size_t)row1 * DD + col] = o;
            }
        }
    }
}

// ---------------- launch ----------------
extern "C" void kernel_launch(void* const* d_in, const int* in_sizes, int n_in,
                              void* d_out, int out_size)
{
    const float* x     = (const float*)d_in[0];
    const int*   ei    = (const int*)  d_in[1];
    const int*   etype = (const int*)  d_in[2];
    const float* w     = (const float*)d_in[3];   // [768,128]
    const float* qv    = (const float*)d_in[4];
    const float* kv    = (const float*)d_in[5];
    const float* bias  = (const float*)d_in[6];

    float* out       = (float*)d_out;
    float* alpha_out = out + (size_t)NN * DD;

    init_counts_kernel<<<(NN + 255) / 256, 256>>>();
    hist_kernel<<<(EE + 255) / 256, 256>>>(ei);
    {
        dim3 tg(32, 8);
        dim3 bg(DD / 32, KK / 32);
        wt_kernel<<<bg, tg>>>(w);                 // overlaps CSR chain cost-wise
    }
    scan_kernel<<<1, 1024>>>();
    scatter_kernel<<<(EE + 255) / 256, 256>>>(ei, etype);

    cqck_kernel<<<(KK * 32 + 255) / 256, 256>>>(w, qv, kv);
    nqnk_kernel<<<(NN * 32 + 255) / 256, 256>>>(x);

    node_kernel<<<(NN * 32 + 255) / 256, 256>>>(x, alpha_out);

    gemm_tc_kernel<<<(NN + GBM - 1) / GBM, 256>>>(x, bias, out);
}

// round 5
// speedup vs baseline: 2.8489x; 1.3302x over previous
#include <cuda_runtime.h>
#include <cuda_bf16.h>
#include <math_constants.h>
#include <cstdint>

#define NN 50000
#define EE 1200000
#define DD 128
#define RR 6
#define KK (RR * DD)   // 768
#define NEG_SLOPE 0.2f

#define SCAN_NB 196    // ceil(50000/256)

// ---------------- scratch ----------------
__device__ __nv_bfloat16 g_Tb[(size_t)NN * KK];  // [n][r*128+d] bf16 (76.8 MB)
__device__ __nv_bfloat16 g_wt[(size_t)DD * KK];  // W^T as [128][768] bf16
__device__ float g_logit[EE];
__device__ int   g_csr[EE];
__device__ int   g_se[EE];
__device__ float g_nqk[NN * 12];
__device__ float g_cq[KK];
__device__ float g_ck[KK];
__device__ int   g_rowstart[NN + 1];
__device__ int   g_cursor[NN];
__device__ int   g_counts[NN];
__device__ int   g_bsum[SCAN_NB];
__device__ int   g_boff[SCAN_NB];

// ---------------- CSR build ----------------
__global__ void init_counts_kernel() {
    int i = blockIdx.x * blockDim.x + threadIdx.x;
    if (i < NN) g_counts[i] = 0;
}

__global__ void hist_kernel(const int* __restrict__ ei) {
    int e = blockIdx.x * blockDim.x + threadIdx.x;
    if (e < EE) atomicAdd(&g_counts[ei[EE + e]], 1);
}

// A: per-block exclusive scan of counts; block sums out
__global__ __launch_bounds__(256) void scanA_kernel() {
    __shared__ int sh[256];
    int t = threadIdx.x;
    int i = blockIdx.x * 256 + t;
    int v = (i < NN) ? g_counts[i] : 0;
    sh[t] = v;
    __syncthreads();
#pragma unroll
    for (int off = 1; off < 256; off <<= 1) {
        int u = (t >= off) ? sh[t - off] : 0;
        __syncthreads();
        sh[t] += u;
        __syncthreads();
    }
    if (i < NN) g_rowstart[i] = sh[t] - v;      // exclusive within block
    if (t == 255) g_bsum[blockIdx.x] = sh[255]; // block total
}

// B: single-block exclusive scan of the 196 block sums
__global__ __launch_bounds__(256) void scanB_kernel() {
    __shared__ int sh[256];
    int t = threadIdx.x;
    int v = (t < SCAN_NB) ? g_bsum[t] : 0;
    sh[t] = v;
    __syncthreads();
#pragma unroll
    for (int off = 1; off < 256; off <<= 1) {
        int u = (t >= off) ? sh[t - off] : 0;
        __syncthreads();
        sh[t] += u;
        __syncthreads();
    }
    if (t < SCAN_NB) g_boff[t] = sh[t] - v;
}

// C: add block offsets; produce rowstart + cursor
__global__ __launch_bounds__(256) void scanC_kernel() {
    int i = blockIdx.x * 256 + threadIdx.x;
    if (i < NN) {
        int v = g_rowstart[i] + g_boff[blockIdx.x];
        g_rowstart[i] = v;
        g_cursor[i]   = v;
    }
    if (i == 0) g_rowstart[NN] = EE;
}

__global__ void scatter_kernel(const int* __restrict__ ei, const int* __restrict__ etype) {
    int e = blockIdx.x * blockDim.x + threadIdx.x;
    if (e < EE) {
        int dst = ei[EE + e];
        int pos = atomicAdd(&g_cursor[dst], 1);
        g_csr[pos] = e;
        g_se[pos]  = ei[e] | (etype[e] << 20);
    }
}

// ---------------- W transpose to bf16: g_wt[n][k] = w[k][n] ----------------
__global__ void wt_kernel(const float* __restrict__ w) {
    __shared__ float tile[32][33];
    int k0 = blockIdx.y * 32;
    int n0 = blockIdx.x * 32;
    int tx = threadIdx.x, ty = threadIdx.y;  // 32 x 8
#pragma unroll
    for (int i = 0; i < 4; i++)
        tile[ty + i * 8][tx] = w[(size_t)(k0 + ty + i * 8) * DD + n0 + tx];
    __syncthreads();
#pragma unroll
    for (int i = 0; i < 4; i++)
        g_wt[(size_t)(n0 + ty + i * 8) * KK + k0 + tx] =
            __float2bfloat16_rn(tile[tx][ty + i * 8]);
}

// ---------------- cq/ck ----------------
__global__ __launch_bounds__(256) void cqck_kernel(
    const float* __restrict__ w, const float* __restrict__ q, const float* __restrict__ k)
{
    int warp = (blockIdx.x * blockDim.x + threadIdx.x) >> 5;
    int lane = threadIdx.x & 31;
    if (warp >= KK) return;
    const float* row = w + (size_t)warp * DD;
    float sq = 0.f, sk = 0.f;
#pragma unroll
    for (int o = lane; o < DD; o += 32) {
        float v = row[o];
        sq = fmaf(v, q[o], sq);
        sk = fmaf(v, k[o], sk);
    }
#pragma unroll
    for (int off = 16; off > 0; off >>= 1) {
        sq += __shfl_xor_sync(0xffffffffu, sq, off);
        sk += __shfl_xor_sync(0xffffffffu, sk, off);
    }
    if (lane == 0) { g_cq[warp] = sq; g_ck[warp] = sk; }
}

// ---------------- nq/nk ----------------
__global__ __launch_bounds__(256) void nqnk_kernel(const float* __restrict__ x)
{
    int warp = (blockIdx.x * blockDim.x + threadIdx.x) >> 5;
    int lane = threadIdx.x & 31;
    if (warp >= NN) return;
    const int n = warp;
    const float4 xv = *(const float4*)&x[(size_t)n * DD + lane * 4];
#pragma unroll
    for (int r = 0; r < RR; r++) {
        const float4 cq = *(const float4*)&g_cq[r * DD + lane * 4];
        const float4 ck = *(const float4*)&g_ck[r * DD + lane * 4];
        float sq = xv.x * cq.x + xv.y * cq.y + xv.z * cq.z + xv.w * cq.w;
        float sk = xv.x * ck.x + xv.y * ck.y + xv.z * ck.z + xv.w * ck.w;
#pragma unroll
        for (int off = 16; off > 0; off >>= 1) {
            sq += __shfl_xor_sync(0xffffffffu, sq, off);
            sk += __shfl_xor_sync(0xffffffffu, sk, off);
        }
        if (lane == 0) {
            g_nqk[n * 12 + r * 2]     = sq;
            g_nqk[n * 12 + r * 2 + 1] = sk;
        }
    }
}

// ---------------- node softmax + weighted-x aggregation -> bf16 T ----------------
__device__ __forceinline__ float sel6(int et, float v0, float v1, float v2,
                                      float v3, float v4, float v5) {
    float v = v0;
    v = (et == 1) ? v1 : v;
    v = (et == 2) ? v2 : v;
    v = (et == 3) ? v3 : v;
    v = (et == 4) ? v4 : v;
    v = (et == 5) ? v5 : v;
    return v;
}

__device__ __forceinline__ void accum6(float4 (&acc)[RR], int et, float a, float4 v) {
    switch (et) {
        case 0: acc[0].x = fmaf(a, v.x, acc[0].x); acc[0].y = fmaf(a, v.y, acc[0].y);
                acc[0].z = fmaf(a, v.z, acc[0].z); acc[0].w = fmaf(a, v.w, acc[0].w); break;
        case 1: acc[1].x = fmaf(a, v.x, acc[1].x); acc[1].y = fmaf(a, v.y, acc[1].y);
                acc[1].z = fmaf(a, v.z, acc[1].z); acc[1].w = fmaf(a, v.w, acc[1].w); break;
        case 2: acc[2].x = fmaf(a, v.x, acc[2].x); acc[2].y = fmaf(a, v.y, acc[2].y);
                acc[2].z = fmaf(a, v.z, acc[2].z); acc[2].w = fmaf(a, v.w, acc[2].w); break;
        case 3: acc[3].x = fmaf(a, v.x, acc[3].x); acc[3].y = fmaf(a, v.y, acc[3].y);
                acc[3].z = fmaf(a, v.z, acc[3].z); acc[3].w = fmaf(a, v.w, acc[3].w); break;
        case 4: acc[4].x = fmaf(a, v.x, acc[4].x); acc[4].y = fmaf(a, v.y, acc[4].y);
                acc[4].z = fmaf(a, v.z, acc[4].z); acc[4].w = fmaf(a, v.w, acc[4].w); break;
        default: acc[5].x = fmaf(a, v.x, acc[5].x); acc[5].y = fmaf(a, v.y, acc[5].y);
                acc[5].z = fmaf(a, v.z, acc[5].z); acc[5].w = fmaf(a, v.w, acc[5].w); break;
    }
}

__global__ __launch_bounds__(256) void node_kernel(
    const float* __restrict__ x, float* __restrict__ alpha_out)
{
    int warp = (blockIdx.x * blockDim.x + threadIdx.x) >> 5;
    int lane = threadIdx.x & 31;
    if (warp >= NN) return;
    const int n = warp;
    const int s = g_rowstart[n];
    const int e = g_rowstart[n + 1];

    const float nq0 = g_nqk[n * 12 + 0];
    const float nq1 = g_nqk[n * 12 + 2];
    const float nq2 = g_nqk[n * 12 + 4];
    const float nq3 = g_nqk[n * 12 + 6];
    const float nq4 = g_nqk[n * 12 + 8];
    const float nq5 = g_nqk[n * 12 + 10];

    float lm = -CUDART_INF_F;
    float ls = 0.f;
    for (int j0 = s; j0 < e; j0 += 32) {
        int j = j0 + lane;
        if (j < e) {
            int se  = g_se[j];
            int src = se & 0xFFFFF;
            int et  = se >> 20;
            float nk = __ldg(&g_nqk[src * 12 + et * 2 + 1]);
            float nq = sel6(et, nq0, nq1, nq2, nq3, nq4, nq5);
            float lg = nq + nk;
            lg = (lg > 0.f) ? lg : NEG_SLOPE * lg;
            g_logit[j] = lg;
            float nlm = fmaxf(lm, lg);
            ls = ls * __expf(lm - nlm) + __expf(lg - nlm);
            lm = nlm;
        }
    }
    float m = lm;
#pragma unroll
    for (int o = 16; o > 0; o >>= 1) m = fmaxf(m, __shfl_xor_sync(0xffffffffu, m, o));
    float contrib = (ls > 0.f) ? ls * __expf(lm - m) : 0.f;
    float dsum = contrib;
#pragma unroll
    for (int o = 16; o > 0; o >>= 1) dsum += __shfl_xor_sync(0xffffffffu, dsum, o);
    const float invden = 1.f / (dsum + 1e-16f);

    float4 acc[RR];
#pragma unroll
    for (int r = 0; r < RR; r++) acc[r] = make_float4(0.f, 0.f, 0.f, 0.f);

    for (int base = s; base < e; base += 32) {
        int j = base + lane;
        int se = 0;
        float a = 0.f;
        if (j < e) {
            se = g_se[j];
            a  = __expf(g_logit[j] - m) * invden;
            alpha_out[g_csr[j]] = a;
        }
        int cnt = e - base; if (cnt > 32) cnt = 32;
        int rounds = (cnt + 3) & ~3;
        for (int t = 0; t < rounds; t += 4) {
            int   se0 = __shfl_sync(0xffffffffu, se, t);
            int   se1 = __shfl_sync(0xffffffffu, se, t + 1);
            int   se2 = __shfl_sync(0xffffffffu, se, t + 2);
            int   se3 = __shfl_sync(0xffffffffu, se, t + 3);
            float a0  = __shfl_sync(0xffffffffu, a,  t);
            float a1  = __shfl_sync(0xffffffffu, a,  t + 1);
            float a2  = __shfl_sync(0xffffffffu, a,  t + 2);
            float a3  = __shfl_sync(0xffffffffu, a,  t + 3);
            const float4 x0 = __ldg((const float4*)&x[(size_t)(se0 & 0xFFFFF) * DD + lane * 4]);
            const float4 x1 = __ldg((const float4*)&x[(size_t)(se1 & 0xFFFFF) * DD + lane * 4]);
            const float4 x2 = __ldg((const float4*)&x[(size_t)(se2 & 0xFFFFF) * DD + lane * 4]);
            const float4 x3 = __ldg((const float4*)&x[(size_t)(se3 & 0xFFFFF) * DD + lane * 4]);
            accum6(acc, se0 >> 20, a0, x0);
            accum6(acc, se1 >> 20, a1, x1);
            accum6(acc, se2 >> 20, a2, x2);
            accum6(acc, se3 >> 20, a3, x3);
        }
    }

#pragma unroll
    for (int r = 0; r < RR; r++) {
        __nv_bfloat162 lo = __floats2bfloat162_rn(acc[r].x, acc[r].y);
        __nv_bfloat162 hi = __floats2bfloat162_rn(acc[r].z, acc[r].w);
        uint2 pk = make_uint2(*(uint32_t*)&lo, *(uint32_t*)&hi);
        *(uint2*)&g_Tb[(size_t)n * KK + r * DD + lane * 4] = pk;
    }
}

// ---------------- bf16 tensor-core GEMM: out = T @ W + bias + x ----------------
#define GBM 128
#define GBK 64
#define SSTR 72

__global__ __launch_bounds__(256) void gemm_tc_kernel(
    const float* __restrict__ x, const float* __restrict__ bias, float* __restrict__ out)
{
    __shared__ __nv_bfloat16 As[GBM][SSTR];
    __shared__ __nv_bfloat16 Bs[DD][SSTR];

    const int m0   = blockIdx.x * GBM;
    const int t    = threadIdx.x;
    const int warp = t >> 5;
    const int lane = t & 31;
    const int g    = lane >> 2;
    const int tig  = lane & 3;
    const int R0   = (warp & 3) * 32;
    const int C0   = (warp >> 2) * 64;

    float acc[2][8][4];
#pragma unroll
    for (int mt = 0; mt < 2; mt++)
#pragma unroll
        for (int nt = 0; nt < 8; nt++)
#pragma unroll
            for (int i = 0; i < 4; i++) acc[mt][nt][i] = 0.f;

    for (int k0 = 0; k0 < KK; k0 += GBK) {
#pragma unroll
        for (int i = t; i < GBM * GBK / 8; i += 256) {
            int row = i >> 3, c8 = i & 7;
            int gr = m0 + row;
            uint4 v = make_uint4(0, 0, 0, 0);
            if (gr < NN) v = *(const uint4*)&g_Tb[(size_t)gr * KK + k0 + c8 * 8];
            *(uint4*)&As[row][c8 * 8] = v;
        }
#pragma unroll
        for (int i = t; i < DD * GBK / 8; i += 256) {
            int row = i >> 3, c8 = i & 7;
            *(uint4*)&Bs[row][c8 * 8] = *(const uint4*)&g_wt[(size_t)row * KK + k0 + c8 * 8];
        }
        __syncthreads();

#pragma unroll
        for (int ks = 0; ks < GBK; ks += 16) {
            uint32_t af[2][4];
#pragma unroll
            for (int mt = 0; mt < 2; mt++) {
                int rb = R0 + mt * 16;
                af[mt][0] = *(const uint32_t*)&As[rb + g][ks + 2 * tig];
                af[mt][1] = *(const uint32_t*)&As[rb + g + 8][ks + 2 * tig];
                af[mt][2] = *(const uint32_t*)&As[rb + g][ks + 8 + 2 * tig];
                af[mt][3] = *(const uint32_t*)&As[rb + g + 8][ks + 8 + 2 * tig];
            }
#pragma unroll
            for (int nt = 0; nt < 8; nt++) {
                int cb = C0 + nt * 8 + g;
                uint32_t b0 = *(const uint32_t*)&Bs[cb][ks + 2 * tig];
                uint32_t b1 = *(const uint32_t*)&Bs[cb][ks + 8 + 2 * tig];
#pragma unroll
                for (int mt = 0; mt < 2; mt++) {
                    asm volatile(
                        "mma.sync.aligned.m16n8k16.row.col.f32.bf16.bf16.f32 "
                        "{%0,%1,%2,%3}, {%4,%5,%6,%7}, {%8,%9}, {%0,%1,%2,%3};"
                        : "+f"(acc[mt][nt][0]), "+f"(acc[mt][nt][1]),
                          "+f"(acc[mt][nt][2]), "+f"(acc[mt][nt][3])
                        : "r"(af[mt][0]), "r"(af[mt][1]), "r"(af[mt][2]), "r"(af[mt][3]),
                          "r"(b0), "r"(b1));
                }
            }
        }
        __syncthreads();
    }

#pragma unroll
    for (int mt = 0; mt < 2; mt++) {
        int row0 = m0 + R0 + mt * 16 + g;
        int row1 = row0 + 8;
#pragma unroll
        for (int nt = 0; nt < 8; nt++) {
            int col = C0 + nt * 8 + 2 * tig;
            float2 b = *(const float2*)&bias[col];
            if (row0 < NN) {
                const float2 xr = *(const float2*)&x[(size_t)row0 * DD + col];
                float2 o;
                o.x = acc[mt][nt][0] + b.x + xr.x;
                o.y = acc[mt][nt][1] + b.y + xr.y;
                *(float2*)&out[(size_t)row0 * DD + col] = o;
            }
            if (row1 < NN) {
                const float2 xr = *(const float2*)&x[(size_t)row1 * DD + col];
                float2 o;
                o.x = acc[mt][nt][2] + b.x + xr.x;
                o.y = acc[mt][nt][3] + b.y + xr.y;
                *(float2*)&out[(size_t)row1 * DD + col] = o;
            }
        }
    }
}

// ---------------- launch ----------------
extern "C" void kernel_launch(void* const* d_in, const int* in_sizes, int n_in,
                              void* d_out, int out_size)
{
    const float* x     = (const float*)d_in[0];
    const int*   ei    = (const int*)  d_in[1];
    const int*   etype = (const int*)  d_in[2];
    const float* w     = (const float*)d_in[3];
    const float* qv    = (const float*)d_in[4];
    const float* kv    = (const float*)d_in[5];
    const float* bias  = (const float*)d_in[6];

    float* out       = (float*)d_out;
    float* alpha_out = out + (size_t)NN * DD;

    init_counts_kernel<<<(NN + 255) / 256, 256>>>();
    hist_kernel<<<(EE + 255) / 256, 256>>>(ei);
    {
        dim3 tg(32, 8);
        dim3 bg(DD / 32, KK / 32);
        wt_kernel<<<bg, tg>>>(w);
    }
    scanA_kernel<<<SCAN_NB, 256>>>();
    scanB_kernel<<<1, 256>>>();
    scanC_kernel<<<SCAN_NB, 256>>>();
    scatter_kernel<<<(EE + 255) / 256, 256>>>(ei, etype);

    cqck_kernel<<<(KK * 32 + 255) / 256, 256>>>(w, qv, kv);
    nqnk_kernel<<<(NN * 32 + 255) / 256, 256>>>(x);

    node_kernel<<<(NN * 32 + 255) / 256, 256>>>(x, alpha_out);

    gemm_tc_kernel<<<(NN + GBM - 1) / GBM, 256>>>(x, bias, out);
}